// round 4
// baseline (speedup 1.0000x reference)
#include <cuda_runtime.h>
#include <math.h>
#include <limits.h>

// Fixed problem shape (setup_inputs): B=8, P=512, Q=4096, H=W=512
#define B_   8
#define P_   512
#define Q_   4096
#define N_   4096
#define R_   45
#define HW_  512
#define NBINS 8          // y-strips of 64 px

#define PTS_BLOCKS 512   // 8 query-warps per block
#define CE_BLOCKS  64
#define TOTAL_BLOCKS (PTS_BLOCKS + CE_BLOCKS)

__device__ float        g_pts_part[PTS_BLOCKS];
__device__ float        g_ce_num[CE_BLOCKS];
__device__ float        g_ce_den[CE_BLOCKS];
__device__ unsigned int g_done;          // 0 at load; final block self-resets

__device__ __forceinline__ float softplusf(float d) {
    return fmaxf(d, 0.f) + log1pf(expf(-fabsf(d)));
}

__global__ void __launch_bounds__(256) k_fused(
    const float* __restrict__ tp,
    const float* __restrict__ sp,
    const float* __restrict__ logits,
    const int*   __restrict__ sidx,
    float* __restrict__ out)
{
    __shared__ int      s_pts[P_];          // y-binned, packed px | py<<16
    __shared__ int      s_cnt[NBINS];
    __shared__ int      s_off[NBINS + 1];
    __shared__ float    sm[256];
    __shared__ unsigned bm[Q_ / 32];
    __shared__ int      s_last;

    const int tid = threadIdx.x;
    const int bid = blockIdx.x;

    if (bid < PTS_BLOCKS) {
        // ========== points focal loss: counting-sort by y-strip, then scan ==========
        const int b = bid >> 6;

        if (tid < NBINS) s_cnt[tid] = 0;
        __syncthreads();

        // each thread owns two points (one float4)
        int pkA, pkB, binA, binB, rkA, rkB;
        {
            float4 v = ((const float4*)(tp + (size_t)b * P_ * 2))[tid];
            int pxa = min(max((int)rintf(v.x), 0), HW_ - 1);
            int pya = min(max((int)rintf(v.y), 0), HW_ - 1);
            int pxb = min(max((int)rintf(v.z), 0), HW_ - 1);
            int pyb = min(max((int)rintf(v.w), 0), HW_ - 1);
            pkA = pxa | (pya << 16);  binA = pya >> 6;
            pkB = pxb | (pyb << 16);  binB = pyb >> 6;
            rkA = atomicAdd(&s_cnt[binA], 1);
            rkB = atomicAdd(&s_cnt[binB], 1);
        }
        __syncthreads();
        if (tid == 0) {                      // tiny exclusive scan over 8 bins
            int acc = 0;
            #pragma unroll
            for (int i = 0; i < NBINS; i++) { s_off[i] = acc; acc += s_cnt[i]; }
            s_off[NBINS] = acc;              // == 512
        }
        __syncthreads();
        s_pts[s_off[binA] + rkA] = pkA;
        s_pts[s_off[binB] + rkB] = pkB;
        __syncthreads();

        const int warp = tid >> 5, lane = tid & 31;
        const int q = bid * 8 + warp;

        float x = fminf(fmaxf(sp[2 * q]     * (float)HW_, 0.f), (float)(HW_ - 1));
        float y = fminf(fmaxf(sp[2 * q + 1] * (float)HW_, 0.f), (float)(HW_ - 1));
        float x0f = floorf(x), y0f = floorf(y);
        int x0 = (int)x0f, y0 = (int)y0f;
        float wx = x - x0f, wy = y - y0f;

        // relevant py range for the 2x2 corners: [y0-45, y0+46]
        int blo = max(y0 - R_, 0) >> 6;
        int bhi = min(y0 + R_ + 1, HW_ - 1) >> 6;
        int jend = s_off[bhi + 1];

        int m00 = INT_MAX, m01 = INT_MAX, m10 = INT_MAX, m11 = INT_MAX;
        for (int j = s_off[blo] + lane; j < jend; j += 32) {
            int w  = s_pts[j];
            int px = w & 0xFFFF, py = w >> 16;
            int dx0 = x0 - px,  dy0 = y0 - py;
            int ax  = dx0 + R_, ay  = dy0 + R_;
            bool cx0 = (unsigned)ax       <= 2u * R_;
            bool cx1 = (unsigned)(ax + 1) <= 2u * R_;
            bool cy0 = (unsigned)ay       <= 2u * R_;
            bool cy1 = (unsigned)(ay + 1) <= 2u * R_;
            int a0 = dx0 * dx0;
            int a1 = (dx0 + 1) * (dx0 + 1);
            int e0 = dy0 * dy0;
            int e1 = (dy0 + 1) * (dy0 + 1);
            if (cx0 && cy0) m00 = min(m00, a0 + e0);
            if (cx1 && cy0) m01 = min(m01, a1 + e0);
            if (cx0 && cy1) m10 = min(m10, a0 + e1);
            if (cx1 && cy1) m11 = min(m11, a1 + e1);
        }
        m00 = (int)__reduce_min_sync(0xffffffffu, (unsigned)m00);
        m01 = (int)__reduce_min_sync(0xffffffffu, (unsigned)m01);
        m10 = (int)__reduce_min_sync(0xffffffffu, (unsigned)m10);
        m11 = (int)__reduce_min_sync(0xffffffffu, (unsigned)m11);

        if (lane == 0) {
            const float inv = 1.0f / (2.0f * 15.0f * 15.0f);
            float v00 = (m00 == INT_MAX) ? 0.f : expf(-(float)m00 * inv);
            float v01 = (m01 == INT_MAX) ? 0.f : expf(-(float)m01 * inv);
            float v10 = (m10 == INT_MAX) ? 0.f : expf(-(float)m10 * inv);
            float v11 = (m11 == INT_MAX) ? 0.f : expf(-(float)m11 * inv);
            float p = v00 * (1.f - wx) * (1.f - wy) + v01 * wx * (1.f - wy)
                    + v10 * (1.f - wx) * wy         + v11 * wx * wy;
            float om = 1.f - p;
            sm[warp] = -om * om * logf(fmaxf(p, 1e-6f));
        }
        __syncthreads();
        if (tid == 0) {
            float s = 0.f;
            #pragma unroll
            for (int k = 0; k < 8; k++) s += sm[k];
            g_pts_part[bid] = s;
        }
    } else {
        // ====== CE: weighted cross-entropy, one block per 512-query slice ======
        const int cb = bid - PTS_BLOCKS;
        const int b  = cb >> 3;
        const int s  = cb & 7;

        if (tid < Q_ / 32) bm[tid] = 0u;
        __syncthreads();
        {
            int i0 = sidx[b * P_ + tid];
            int i1 = sidx[b * P_ + 256 + tid];
            atomicOr(&bm[i0 >> 5], 1u << (i0 & 31));
            atomicOr(&bm[i1 >> 5], 1u << (i1 & 31));
        }
        __syncthreads();

        float4 l = ((const float4*)(logits + (size_t)b * Q_ * 2 + s * 1024))[tid];
        int q0 = s * 512 + 2 * tid, q1 = q0 + 1;
        bool f0 = (bm[q0 >> 5] >> (q0 & 31)) & 1u;
        bool f1 = (bm[q1 >> 5] >> (q1 & 31)) & 1u;
        float d0 = l.y - l.x, d1 = l.w - l.z;
        float num = (f0 ? softplusf(-d0) : 0.5f * softplusf(d0))
                  + (f1 ? softplusf(-d1) : 0.5f * softplusf(d1));
        float den = (f0 ? 1.f : 0.5f) + (f1 ? 1.f : 0.5f);

        sm[tid] = num; __syncthreads();
        for (int o = 128; o; o >>= 1) { if (tid < o) sm[tid] += sm[tid + o]; __syncthreads(); }
        if (tid == 0) g_ce_num[cb] = sm[0];
        __syncthreads();
        sm[tid] = den; __syncthreads();
        for (int o = 128; o; o >>= 1) { if (tid < o) sm[tid] += sm[tid + o]; __syncthreads(); }
        if (tid == 0) g_ce_den[cb] = sm[0];
    }

    // ---------------- last-block-done finalize ----------------
    __syncthreads();
    if (tid == 0) {
        __threadfence();
        unsigned int prev = atomicAdd(&g_done, 1u);
        s_last = (prev == (unsigned)(TOTAL_BLOCKS - 1)) ? 1 : 0;
    }
    __syncthreads();
    if (s_last) {
        volatile float* pp = g_pts_part;
        volatile float* cn = g_ce_num;
        volatile float* cd = g_ce_den;

        float v = pp[tid] + pp[tid + 256];
        sm[tid] = v; __syncthreads();
        for (int o = 128; o; o >>= 1) { if (tid < o) sm[tid] += sm[tid + o]; __syncthreads(); }
        float ptsSum = sm[0]; __syncthreads();

        sm[tid] = (tid < CE_BLOCKS) ? cn[tid] : 0.f; __syncthreads();
        for (int o = 128; o; o >>= 1) { if (tid < o) sm[tid] += sm[tid + o]; __syncthreads(); }
        float ceN = sm[0]; __syncthreads();

        sm[tid] = (tid < CE_BLOCKS) ? cd[tid] : 0.f; __syncthreads();
        for (int o = 128; o; o >>= 1) { if (tid < o) sm[tid] += sm[tid + o]; __syncthreads(); }
        if (tid == 0) {
            float ceD = sm[0];
            out[0] = ceN / ceD + 0.5f * ptsSum / (float)N_;
            g_done = 0u;
        }
    }
}

extern "C" void kernel_launch(void* const* d_in, const int* in_sizes, int n_in,
                              void* d_out, int out_size) {
    const float* tp     = (const float*)d_in[0];
    const float* sp     = (const float*)d_in[1];
    const float* logits = (const float*)d_in[2];
    const int*   sidx   = (const int*)  d_in[4];

    k_fused<<<TOTAL_BLOCKS, 256>>>(tp, sp, logits, sidx, (float*)d_out);
}